// round 12
// baseline (speedup 1.0000x reference)
#include <cuda_runtime.h>
#include <math.h>

#define NMOL 16
#define NATOM 64
#define RADF 64
#define ANGF 320
#define FEAT 384
#define RCR 5.2f
#define RCA 3.5f
#define FULL 0xffffffffu
#define TPB 256
#define PAIRMAX 512

__constant__ int c_triu16[16] = {
    0,1,2,3,
    1,4,5,6,
    2,5,7,8,
    3,6,8,9
};
// cos/sin of SHF_Z[z] = pi/16*(1+2z)
__constant__ float c_cz[8] = {
     0.980785280403230449f,  0.831469612302545237f,  0.555570233019602225f,
     0.195090322016128268f, -0.195090322016128268f, -0.555570233019602225f,
    -0.831469612302545237f, -0.980785280403230449f
};
__constant__ float c_sz[8] = {
     0.195090322016128268f,  0.555570233019602225f,  0.831469612302545237f,
     0.980785280403230449f,  0.980785280403230449f,  0.831469612302545237f,
     0.555570233019602225f,  0.195090322016128268f
};

__device__ __forceinline__ float pow32(float u) {
    u = fmaxf(u, 0.0f);
    u = u * u; u = u * u; u = u * u; u = u * u; u = u * u;
    return u;
}

// closed-form unordered-pair decode (validated R10/R11)
__device__ __forceinline__ void decode_pair(int p, int npairs, int m_a,
                                            int& jj, int& kk) {
    const int t_ = npairs - 1 - p;
    int K = (int)((__fsqrt_rn((float)(8 * t_ + 1)) - 1.0f) * 0.5f);
    K += ((K + 1) * (K + 2) / 2 <= t_) ? 1 : 0;
    K -= (K * (K + 1) / 2 > t_) ? 1 : 0;
    jj = m_a - 2 - K;
    kk = m_a - 1 - (t_ - K * (K + 1) / 2);
}

__global__ __launch_bounds__(TPB)
void aev_kernel(const int* __restrict__ species,
                const float* __restrict__ coords,
                float* __restrict__ out,
                int aev_base, int write_species)
{
    const int atom = blockIdx.x;          // 0..1023
    const int n = atom >> 6;
    const int i = atom & 63;
    const int tid  = threadIdx.x;
    const int lane = tid & 31;
    const int w    = tid >> 5;

    __shared__ float4 sP[NATOM];          // dx,dy,dz,d               (angular)
    __shared__ float4 sQ[NATOM];          // rinv, sqrt2*fca, spec, - (angular)
    __shared__ float4 sR[NATOM];          // d, 0.25*fcr, spec, -     (radial)
    __shared__ int    sPair[PAIRMAX];     // jj | kk<<8 | pidx<<16
    __shared__ float  s_ang[ANGF];        // angular accumulators
    __shared__ float  pR[16 * 68];        // radial partials (pitch 68)
    __shared__ int    sM[2];              // m_r, m_a

    // warps 1-7 zero angular accumulators while warp 0 runs the prologue
    if (w != 0) {
        for (int f = tid - 32; f < ANGF; f += TPB - 32) s_ang[f] = 0.0f;
    }

    // ============ prologue: warp 0, dual-half (R4-validated) ============
    if (w == 0) {
        const float* cb = coords + (size_t)n * NATOM * 3;
        const float x1 = cb[lane * 3 + 0];
        const float y1 = cb[lane * 3 + 1];
        const float z1 = cb[lane * 3 + 2];
        const float x2 = cb[(lane + 32) * 3 + 0];
        const float y2 = cb[(lane + 32) * 3 + 1];
        const float z2 = cb[(lane + 32) * 3 + 2];
        const int   sp1 = species[n * NATOM + lane];
        const int   sp2 = species[n * NATOM + lane + 32];

        const bool ilo = (i < 32);
        const float xi = __shfl_sync(FULL, ilo ? x1 : x2, i & 31);
        const float yi = __shfl_sync(FULL, ilo ? y1 : y2, i & 31);
        const float zi = __shfl_sync(FULL, ilo ? z1 : z2, i & 31);
        const int   si = __shfl_sync(FULL, ilo ? sp1 : sp2, i & 31);

        const float dxl = x1 - xi, dyl = y1 - yi, dzl = z1 - zi;
        const float dxh = x2 - xi, dyh = y2 - yi, dzh = z2 - zi;
        const float d2l = fmaxf(dxl*dxl + dyl*dyl + dzl*dzl, 1e-20f);
        const float d2h = fmaxf(dxh*dxh + dyh*dyh + dzh*dzh, 1e-20f);
        const float rl = rsqrtf(d2l), rh = rsqrtf(d2h);
        const float dl = d2l * rl,    dh = d2h * rh;

        const bool selfl = (lane == i);
        const bool selfh = (lane + 32 == i);
        const bool vRl = !selfl && (dl <= RCR);
        const bool vRh = !selfh && (dh <= RCR);
        const bool vAl = !selfl && (dl <= RCA);
        const bool vAh = !selfh && (dh <= RCA);

        const float PIA = (float)M_PI / RCA, PIR = (float)M_PI / RCR;
        const float fcal = 0.5f * __cosf(PIA * dl) + 0.5f;
        const float fcah = 0.5f * __cosf(PIA * dh) + 0.5f;
        const float hrl  = 0.25f * (0.5f * __cosf(PIR * dl) + 0.5f);
        const float hrh  = 0.25f * (0.5f * __cosf(PIR * dh) + 0.5f);

        const unsigned lt  = (1u << lane) - 1u;
        const unsigned mRl = __ballot_sync(FULL, vRl);
        const unsigned mRh = __ballot_sync(FULL, vRh);
        const unsigned mAl = __ballot_sync(FULL, vAl);
        const unsigned mAh = __ballot_sync(FULL, vAh);

        if (vRl) { int q = __popc(mRl & lt);
            sR[q] = make_float4(dl, hrl, __int_as_float(sp1), 0.f); }
        if (vRh) { int q = __popc(mRl) + __popc(mRh & lt);
            sR[q] = make_float4(dh, hrh, __int_as_float(sp2), 0.f); }
        if (vAl) { int q = __popc(mAl & lt);
            sP[q] = make_float4(dxl, dyl, dzl, dl);
            sQ[q] = make_float4(rl, 1.41421356237f * fcal, __int_as_float(sp1), 0.f); }
        if (vAh) { int q = __popc(mAl) + __popc(mAh & lt);
            sP[q] = make_float4(dxh, dyh, dzh, dh);
            sQ[q] = make_float4(rh, 1.41421356237f * fcah, __int_as_float(sp2), 0.f); }

        const int m_r = __popc(mRl) + __popc(mRh);
        const int m_a = __popc(mAl) + __popc(mAh);
        if (lane == 0) {
            sM[0] = m_r; sM[1] = m_a;
            if (write_species) out[atom] = (float)si;
        }
        __syncwarp();                       // sQ visible within warp

        // build packed pair list (one decode per pair, done once)
        const int npairs = m_a * (m_a - 1) / 2;
        const int nlist  = min(npairs, PAIRMAX);
        for (int p = lane; p < nlist; p += 32) {
            int jj, kk;
            decode_pair(p, npairs, m_a, jj, kk);
            const int pidx = c_triu16[__float_as_int(sQ[jj].z) * 4 +
                                      __float_as_int(sQ[kk].z)];
            sPair[p] = jj | (kk << 8) | (pidx << 16);
        }
    }
    __syncthreads();                        // lists + pair list + zeroed s_ang

    const int m_r = sM[0];
    const int m_a = sM[1];

    // ============ radial: register accum, no atomics ============
    {
        const int r = tid & 15;
        const int g = tid >> 4;             // 0..15
        const float shf = 0.9f + 0.26875f * (float)r;
        float a0 = 0.f, a1 = 0.f, a2 = 0.f, a3 = 0.f;
        for (int q = g; q < m_r; q += 16) {
            const float4 e = sR[q];
            const int s = __float_as_int(e.z);
            const float t = e.x - shf;
            const float v = __expf(-16.0f * t * t) * e.y;
            a0 += (s == 0) ? v : 0.f;
            a1 += (s == 1) ? v : 0.f;
            a2 += (s == 2) ? v : 0.f;
            a3 += (s == 3) ? v : 0.f;
        }
        pR[g * 68 +  0 + r] = a0;
        pR[g * 68 + 16 + r] = a1;
        pR[g * 68 + 32 + r] = a2;
        pR[g * 68 + 48 + r] = a3;
    }

    // ============ angular: warp-per-pair, lane = (a,z) feature ============
    {
        const float sha = 0.9f + 0.65f * (float)(lane >> 3);
        const float cz = c_cz[lane & 7], sz = c_sz[lane & 7];
        const int npairs = m_a * (m_a - 1) / 2;
        for (int p = w; p < npairs; p += 8) {
            int jj, kk, pidx;
            if (p < PAIRMAX) {
                const int e = sPair[p];
                jj = e & 0xff; kk = (e >> 8) & 0xff; pidx = e >> 16;
            } else {
                decode_pair(p, npairs, m_a, jj, kk);
                pidx = c_triu16[__float_as_int(sQ[jj].z) * 4 +
                                __float_as_int(sQ[kk].z)];
            }

            const float4 Pj = sP[jj], Qj = sQ[jj];
            const float4 Pk = sP[kk], Qk = sQ[kk];

            const float dot = Pj.x * Pk.x + Pj.y * Pk.y + Pj.z * Pk.z;
            float c = 0.95f * dot * Qj.x * Qk.x;
            c = fminf(0.95f, fmaxf(-0.95f, c));
            const float s = sqrtf(1.0f - c * c);
            const float davg = 0.5f * (Pj.w + Pk.w);
            const float t2 = davg - sha;
            const float f2 = __expf(-8.0f * t2 * t2);
            const float f1 = pow32(0.5f * (1.0f + c * cz + s * sz));
            atomicAdd(&s_ang[pidx * 32 + lane], Qj.y * Qk.y * f2 * f1);
        }
    }
    __syncthreads();

    // ============ epilogue: reduce radial partials + store ============
    float* ob = out + aev_base + (size_t)atom * FEAT;
    if (tid < RADF) {
        float sum = 0.f;
        #pragma unroll
        for (int g = 0; g < 16; g++) sum += pR[g * 68 + tid];
        ob[tid] = sum;
    }
    for (int f = tid; f < ANGF; f += TPB) ob[RADF + f] = s_ang[f];
}

extern "C" void kernel_launch(void* const* d_in, const int* in_sizes, int n_in,
                              void* d_out, int out_size)
{
    const int*   species = (const int*)d_in[0];
    const float* coords  = (const float*)d_in[1];
    float* out = (float*)d_out;

    const int total_atoms = NMOL * NATOM;       // 1024
    int aev_base = 0, write_species = 0;
    if (out_size >= total_atoms * FEAT + total_atoms) {
        aev_base = total_atoms;
        write_species = 1;
    }

    aev_kernel<<<total_atoms, TPB>>>(species, coords, out, aev_base, write_species);
}

// round 13
// speedup vs baseline: 1.4090x; 1.4090x over previous
#include <cuda_runtime.h>
#include <math.h>

#define NMOL 16
#define NATOM 64
#define RADF 64
#define ANGF 320
#define FEAT 384
#define RCR 5.2f
#define RCA 3.5f
#define FULL 0xffffffffu
#define TPB 256

__constant__ int c_triu16[16] = {
    0,1,2,3,
    1,4,5,6,
    2,5,7,8,
    3,6,8,9
};
// 0.5*cos / 0.5*sin of SHF_Z[z] = pi/16*(1+2z)
__constant__ float c_hcz[8] = {
     0.490392640201615224f,  0.415734806151272618f,  0.277785116509801112f,
     0.097545161008064134f, -0.097545161008064134f, -0.277785116509801112f,
    -0.415734806151272618f, -0.490392640201615224f
};
__constant__ float c_hsz[8] = {
     0.097545161008064134f,  0.277785116509801112f,  0.415734806151272618f,
     0.490392640201615224f,  0.490392640201615224f,  0.415734806151272618f,
     0.277785116509801112f,  0.097545161008064134f
};

__device__ __forceinline__ float pow32(float u) {
    u = fmaxf(u, 0.0f);
    u = u * u; u = u * u; u = u * u; u = u * u; u = u * u;
    return u;
}

// closed-form unordered-pair decode (validated R10/R11)
__device__ __forceinline__ void decode_pair(int p, int npairs, int m_a,
                                            int& jj, int& kk) {
    const int t_ = npairs - 1 - p;
    int K = (int)((__fsqrt_rn((float)(8 * t_ + 1)) - 1.0f) * 0.5f);
    K += ((K + 1) * (K + 2) / 2 <= t_) ? 1 : 0;
    K -= (K * (K + 1) / 2 > t_) ? 1 : 0;
    jj = m_a - 2 - K;
    kk = m_a - 1 - (t_ - K * (K + 1) / 2);
}

__global__ __launch_bounds__(TPB)
void aev_kernel(const int* __restrict__ species,
                const float* __restrict__ coords,
                float* __restrict__ out,
                int aev_base, int write_species)
{
    const int atom = blockIdx.x;          // 0..1023
    const int n = atom >> 6;
    const int i = atom & 63;
    const int tid  = threadIdx.x;
    const int lane = tid & 31;
    const int w    = tid >> 5;

    __shared__ float4 sP[NATOM];          // dx,dy,dz,d               (angular)
    __shared__ float4 sQ[NATOM];          // rinv, sqrt2*fca, spec, - (angular)
    __shared__ float4 sR[NATOM];          // d, 0.25*fcr, spec, -     (radial)
    __shared__ float  s_ang[ANGF];        // angular accumulators
    __shared__ float  pR[16 * 68];        // radial partials (pitch 68)

    // ===== prologue: ALL warps run dual-half geometry redundantly =====
    const float* cb = coords + (size_t)n * NATOM * 3;
    const float x1 = cb[lane * 3 + 0];
    const float y1 = cb[lane * 3 + 1];
    const float z1 = cb[lane * 3 + 2];
    const float x2 = cb[(lane + 32) * 3 + 0];
    const float y2 = cb[(lane + 32) * 3 + 1];
    const float z2 = cb[(lane + 32) * 3 + 2];
    const int   sp1 = species[n * NATOM + lane];
    const int   sp2 = species[n * NATOM + lane + 32];

    const bool ilo = (i < 32);
    const float xi = __shfl_sync(FULL, ilo ? x1 : x2, i & 31);
    const float yi = __shfl_sync(FULL, ilo ? y1 : y2, i & 31);
    const float zi = __shfl_sync(FULL, ilo ? z1 : z2, i & 31);
    const int   si = __shfl_sync(FULL, ilo ? sp1 : sp2, i & 31);

    const float dxl = x1 - xi, dyl = y1 - yi, dzl = z1 - zi;
    const float dxh = x2 - xi, dyh = y2 - yi, dzh = z2 - zi;
    const float d2l = fmaxf(dxl*dxl + dyl*dyl + dzl*dzl, 1e-20f);
    const float d2h = fmaxf(dxh*dxh + dyh*dyh + dzh*dzh, 1e-20f);
    const float rl = rsqrtf(d2l), rh = rsqrtf(d2h);
    const float dl = d2l * rl,    dh = d2h * rh;

    const bool selfl = (lane == i);
    const bool selfh = (lane + 32 == i);
    const bool vRl = !selfl && (dl <= RCR);
    const bool vRh = !selfh && (dh <= RCR);
    const bool vAl = !selfl && (dl <= RCA);
    const bool vAh = !selfh && (dh <= RCA);

    const unsigned lt  = (1u << lane) - 1u;
    const unsigned mRl = __ballot_sync(FULL, vRl);
    const unsigned mRh = __ballot_sync(FULL, vRh);
    const unsigned mAl = __ballot_sync(FULL, vAl);
    const unsigned mAh = __ballot_sync(FULL, vAh);

    // every warp now knows the counts in-register — no smem exchange
    const int m_r = __popc(mRl) + __popc(mRh);
    const int m_a = __popc(mAl) + __popc(mAh);

    // zero angular accumulators (all warps, fully parallel)
    s_ang[tid < ANGF ? tid : 0] = 0.0f;
    if (tid < ANGF - TPB) s_ang[tid + TPB] = 0.0f;

    // list writes partitioned across warps 0/1/2 (each warp holds all values)
    if (w == 0) {
        const float PIR = (float)M_PI / RCR;
        const float hrl = 0.25f * (0.5f * __cosf(PIR * dl) + 0.5f);
        const float hrh = 0.25f * (0.5f * __cosf(PIR * dh) + 0.5f);
        if (vRl) sR[__popc(mRl & lt)]
            = make_float4(dl, hrl, __int_as_float(sp1), 0.f);
        if (vRh) sR[__popc(mRl) + __popc(mRh & lt)]
            = make_float4(dh, hrh, __int_as_float(sp2), 0.f);
    } else if (w == 1) {
        if (vAl) sP[__popc(mAl & lt)] = make_float4(dxl, dyl, dzl, dl);
        if (vAh) sP[__popc(mAl) + __popc(mAh & lt)] = make_float4(dxh, dyh, dzh, dh);
    } else if (w == 2) {
        const float PIA = (float)M_PI / RCA;
        const float fcal = 0.5f * __cosf(PIA * dl) + 0.5f;
        const float fcah = 0.5f * __cosf(PIA * dh) + 0.5f;
        if (vAl) sQ[__popc(mAl & lt)]
            = make_float4(rl, 1.41421356237f * fcal, __int_as_float(sp1), 0.f);
        if (vAh) sQ[__popc(mAl) + __popc(mAh & lt)]
            = make_float4(rh, 1.41421356237f * fcah, __int_as_float(sp2), 0.f);
    }
    if (write_species && tid == 0) out[atom] = (float)si;
    __syncthreads();                      // single pre-compute barrier

    // ===== radial: register accum, no atomics (R11-validated) =====
    {
        const int r = tid & 15;
        const int g = tid >> 4;           // 0..15
        const float shf = 0.9f + 0.26875f * (float)r;
        float a0 = 0.f, a1 = 0.f, a2 = 0.f, a3 = 0.f;
        for (int q = g; q < m_r; q += 16) {
            const float4 e = sR[q];
            const int s = __float_as_int(e.z);
            const float t = e.x - shf;
            const float v = __expf(-16.0f * t * t) * e.y;
            a0 += (s == 0) ? v : 0.f;
            a1 += (s == 1) ? v : 0.f;
            a2 += (s == 2) ? v : 0.f;
            a3 += (s == 3) ? v : 0.f;
        }
        pR[g * 68 +  0 + r] = a0;
        pR[g * 68 + 16 + r] = a1;
        pR[g * 68 + 32 + r] = a2;
        pR[g * 68 + 48 + r] = a3;
    }

    // ===== angular: warp-per-pair ×2 in flight, lane = (a,z) feature =====
    {
        const float sha = 0.9f + 0.65f * (float)(lane >> 3);
        const float hcz = c_hcz[lane & 7], hsz = c_hsz[lane & 7];
        const int npairs = m_a * (m_a - 1) / 2;

        int p = w * 2;
        for (; p + 1 < npairs; p += 16) {
            int jjA, kkA, jjB, kkB;
            decode_pair(p,     npairs, m_a, jjA, kkA);
            decode_pair(p + 1, npairs, m_a, jjB, kkB);

            const float4 PjA = sP[jjA], QjA = sQ[jjA];
            const float4 PkA = sP[kkA], QkA = sQ[kkA];
            const float4 PjB = sP[jjB], QjB = sQ[jjB];
            const float4 PkB = sP[kkB], QkB = sQ[kkB];
            const int pxA = c_triu16[__float_as_int(QjA.z) * 4 + __float_as_int(QkA.z)];
            const int pxB = c_triu16[__float_as_int(QjB.z) * 4 + __float_as_int(QkB.z)];

            float cA = 0.95f * (PjA.x*PkA.x + PjA.y*PkA.y + PjA.z*PkA.z) * QjA.x * QkA.x;
            float cB = 0.95f * (PjB.x*PkB.x + PjB.y*PkB.y + PjB.z*PkB.z) * QjB.x * QkB.x;
            cA = fminf(0.95f, fmaxf(-0.95f, cA));
            cB = fminf(0.95f, fmaxf(-0.95f, cB));
            const float sA = sqrtf(1.0f - cA * cA);
            const float sB = sqrtf(1.0f - cB * cB);
            const float tA = 0.5f * (PjA.w + PkA.w) - sha;
            const float tB = 0.5f * (PjB.w + PkB.w) - sha;
            const float f2A = __expf(-8.0f * tA * tA);
            const float f2B = __expf(-8.0f * tB * tB);
            const float f1A = pow32(fmaf(cA, hcz, fmaf(sA, hsz, 0.5f)));
            const float f1B = pow32(fmaf(cB, hcz, fmaf(sB, hsz, 0.5f)));
            atomicAdd(&s_ang[pxA * 32 + lane], QjA.y * QkA.y * f2A * f1A);
            atomicAdd(&s_ang[pxB * 32 + lane], QjB.y * QkB.y * f2B * f1B);
        }
        if (p < npairs) {
            int jj, kk;
            decode_pair(p, npairs, m_a, jj, kk);
            const float4 Pj = sP[jj], Qj = sQ[jj];
            const float4 Pk = sP[kk], Qk = sQ[kk];
            const int pidx = c_triu16[__float_as_int(Qj.z) * 4 + __float_as_int(Qk.z)];
            float c = 0.95f * (Pj.x*Pk.x + Pj.y*Pk.y + Pj.z*Pk.z) * Qj.x * Qk.x;
            c = fminf(0.95f, fmaxf(-0.95f, c));
            const float s = sqrtf(1.0f - c * c);
            const float t2 = 0.5f * (Pj.w + Pk.w) - sha;
            const float f2 = __expf(-8.0f * t2 * t2);
            const float f1 = pow32(fmaf(c, hcz, fmaf(s, hsz, 0.5f)));
            atomicAdd(&s_ang[pidx * 32 + lane], Qj.y * Qk.y * f2 * f1);
        }
    }
    __syncthreads();

    // ===== epilogue: reduce radial partials + store =====
    float* ob = out + aev_base + (size_t)atom * FEAT;
    if (tid < RADF) {
        float sum = 0.f;
        #pragma unroll
        for (int g = 0; g < 16; g++) sum += pR[g * 68 + tid];
        ob[tid] = sum;
    }
    for (int f = tid; f < ANGF; f += TPB) ob[RADF + f] = s_ang[f];
}

extern "C" void kernel_launch(void* const* d_in, const int* in_sizes, int n_in,
                              void* d_out, int out_size)
{
    const int*   species = (const int*)d_in[0];
    const float* coords  = (const float*)d_in[1];
    float* out = (float*)d_out;

    const int total_atoms = NMOL * NATOM;       // 1024
    int aev_base = 0, write_species = 0;
    if (out_size >= total_atoms * FEAT + total_atoms) {
        aev_base = total_atoms;
        write_species = 1;
    }

    aev_kernel<<<total_atoms, TPB>>>(species, coords, out, aev_base, write_species);
}